// round 13
// baseline (speedup 1.0000x reference)
#include <cuda_runtime.h>
#include <math.h>

// ---------------- problem dims ----------------
#define B     256
#define NIT   50000
#define E     16
#define SL    10
#define HID   512
#define LAT   64
#define RESPD 1024
#define IN_ENC 1200
#define IN_DEC 1104
#define KE    160
#define ROWS  2560

#define NCH   100
#define CHUNK 500
#define SUBT  250
#define LOG2E 1.4426950408889634f

// pooling tiling: IC=512 -> 65.7KB smem -> 3 blocks/SM
#define IC    512
#define NIC   98
#define UPAD  514
#define SMEM_POOL ((IC*E + 16*UPAD)*4)   // 65664 B

// output layout (float32)
#define OUT_ZM 0
#define OUT_LV 16384
#define OUT_SL 32768
#define OUT_RP 35328

typedef unsigned long long ull;

// ---------------- device scratch ----------------
__device__ float g_x [B*IN_ENC];
__device__ float g_dz[B*IN_DEC];
__device__ float g_rx[B*KE];
__device__ float g_part[4*B*HID];
__device__ float g_upart[NIC*B*17];
__device__ float g_pmax[NCH*ROWS];
__device__ float g_psum[NCH*ROWS];
__device__ int   g_winc[ROWS];
__device__ float g_wmax[ROWS];

__device__ __forceinline__ float ex2f(float x){
    float y; asm("ex2.approx.f32 %0, %1;" : "=f"(y) : "f"(x)); return y;
}
__device__ __forceinline__ float p_lo(ull a){
    return __uint_as_float((unsigned)(a & 0xffffffffull));
}
__device__ __forceinline__ float p_hi(ull a){
    return __uint_as_float((unsigned)(a >> 32));
}
__device__ __forceinline__ ull dup2(float v){
    unsigned u = __float_as_uint(v);
    return (ull)u | ((ull)u << 32);
}

// ---------------- K1: dense pooling partials = (indicator @ emb) via f32x2 ----------------
__global__ __launch_bounds__(256,3) void k_pool(const int* __restrict__ ur,
                                                const float* __restrict__ emb){
    extern __shared__ float sm[];
    float* sh_e = sm;              // IC*16 floats, item-pair interleaved
    float* s_u  = sm + IC*E;       // 16*UPAD floats
    int tid = threadIdx.x;
    int c = blockIdx.x, bg = blockIdx.y;
    int n0 = c*IC;

    for (int t = tid; t < IC*4; t += 256){
        int i = t >> 2, q = t & 3;
        int n = n0 + i;
        float4 v = make_float4(0.f,0.f,0.f,0.f);
        if (n < NIT) v = ((const float4*)emb)[n*4 + q];
        float* dst = sh_e + (i>>1)*32 + (i&1);
        dst[(4*q+0)*2]=v.x; dst[(4*q+1)*2]=v.y; dst[(4*q+2)*2]=v.z; dst[(4*q+3)*2]=v.w;
    }
    for (int t = tid; t < 16*(IC/4); t += 256){
        int bb = t >> 7, j = t & 127;
        int n = n0 + 4*j;
        float4 f = make_float4(0.f,0.f,0.f,0.f);
        if (n < NIT){
            int4 u = ((const int4*)ur)[((size_t)(bg*16+bb)*NIT + n) >> 2];
            f = make_float4((float)u.x,(float)u.y,(float)u.z,(float)u.w);
        }
        float* du = s_u + bb*UPAD + 4*j;
        du[0]=f.x; du[1]=f.y; du[2]=f.z; du[3]=f.w;
    }
    __syncthreads();

    int w = tid >> 5, l = tid & 31;
    int ss = w*2 + (l>>4);
    int bb = l & 15;
    ull acc[E], cnt2 = 0ull;
    #pragma unroll
    for (int e = 0; e < E; e++) acc[e] = 0ull;
    const ulonglong2* e128 = (const ulonglong2*)sh_e;
    const float* urow = s_u + bb*UPAD;
    #pragma unroll 1
    for (int k = 0; k < IC/32; k++){
        int p = ss + 16*k;
        ull u2 = *(const ull*)(urow + 2*p);
        #pragma unroll
        for (int e2 = 0; e2 < 8; e2++){
            ulonglong2 wv = e128[p*8 + e2];
            asm("fma.rn.f32x2 %0, %1, %2, %0;" : "+l"(acc[2*e2])   : "l"(wv.x), "l"(u2));
            asm("fma.rn.f32x2 %0, %1, %2, %0;" : "+l"(acc[2*e2+1]) : "l"(wv.y), "l"(u2));
        }
        asm("add.rn.f32x2 %0, %1, %2;" : "=l"(cnt2) : "l"(cnt2), "l"(u2));
    }
    __syncthreads();
    float* s_part = s_u;
    float* dst = s_part + (ss*16 + bb)*17;
    #pragma unroll
    for (int e = 0; e < E; e++) dst[e] = p_lo(acc[e]) + p_hi(acc[e]);
    dst[16] = p_lo(cnt2) + p_hi(cnt2);
    __syncthreads();
    {
        int b2 = tid >> 4, d = tid & 15;
        float v = 0.f, cv = 0.f;
        #pragma unroll 1
        for (int s2 = 0; s2 < 16; s2++){
            v  += s_part[(s2*16 + b2)*17 + d];
            cv += s_part[(s2*16 + b2)*17 + 16];
        }
        int batch = bg*16 + b2;
        g_upart[((size_t)c*B + batch)*17 + d] = v;
        if (d == 0) g_upart[((size_t)c*B + batch)*17 + 16] = cv;
    }
}

// ---------------- K2: finalize user mean, build x and dz(user/resp) ----------------
__global__ void k_build(const int* __restrict__ slate, const float* __restrict__ resp,
                        const float* __restrict__ emb){
    int b = blockIdx.x, tid = threadIdx.x;
    __shared__ float su[17];
    if (tid < 17){
        float v = 0.f;
        #pragma unroll 1
        for (int c = 0; c < NIC; c++) v += g_upart[((size_t)c*B + b)*17 + tid];
        su[tid] = v;
    }
    __syncthreads();
    float* xr  = g_x  + (size_t)b*IN_ENC;
    float* dzr = g_dz + (size_t)b*IN_DEC;
    if (tid < KE){
        int k = tid >> 4, e = tid & 15;
        xr[tid] = emb[(size_t)slate[b*SL + k]*E + e];
    } else if (tid < KE + E){
        float u = su[tid - KE] / su[16];
        xr[tid] = u;
        dzr[LAT + (tid - KE)] = u;
    }
    for (int j = tid; j < RESPD; j += 256){
        float rv = resp[(size_t)b*RESPD + j];
        xr[KE + E + j]   = rv;
        dzr[LAT + E + j] = rv;
    }
}

// ---------------- split-K fp32 SGEMM ----------------
#define GBM 64
#define GBN 64
#define GBK 16
#define GPAD 4
__global__ void sgemm_part(const float* __restrict__ A, const float* __restrict__ W,
                           float* __restrict__ Cp, int M, int N, int K, int kslice){
    __shared__ __align__(16) float As[GBK][GBM + GPAD];
    __shared__ __align__(16) float Bs[GBK][GBN + GPAD];
    int tid = threadIdx.x;
    int m0 = blockIdx.x * GBM, n0 = blockIdx.y * GBN;
    int kbeg = blockIdx.z * kslice;
    int kend = min(K, kbeg + kslice);
    int tr = tid >> 4, tc = tid & 15;
    int lr = tid >> 2, lk = (tid & 3) * 4;
    float acc[4][4];
    #pragma unroll
    for (int i = 0; i < 4; i++)
        #pragma unroll
        for (int j = 0; j < 4; j++) acc[i][j] = 0.f;

    for (int k0 = kbeg; k0 < kend; k0 += GBK){
        float4 av = *(const float4*)(A + (size_t)(m0 + lr) * K + k0 + lk);
        float4 bv = make_float4(0.f, 0.f, 0.f, 0.f);
        if (n0 + lr < N) bv = *(const float4*)(W + (size_t)(n0 + lr) * K + k0 + lk);
        __syncthreads();
        As[lk+0][lr] = av.x; As[lk+1][lr] = av.y; As[lk+2][lr] = av.z; As[lk+3][lr] = av.w;
        Bs[lk+0][lr] = bv.x; Bs[lk+1][lr] = bv.y; Bs[lk+2][lr] = bv.z; Bs[lk+3][lr] = bv.w;
        __syncthreads();
        #pragma unroll
        for (int kk = 0; kk < GBK; kk++){
            float4 a4 = *(const float4*)&As[kk][tr*4];
            float4 b4 = *(const float4*)&Bs[kk][tc*4];
            float ra[4] = {a4.x, a4.y, a4.z, a4.w};
            float rb[4] = {b4.x, b4.y, b4.z, b4.w};
            #pragma unroll
            for (int i = 0; i < 4; i++)
                #pragma unroll
                for (int j = 0; j < 4; j++)
                    acc[i][j] += ra[i] * rb[j];
        }
    }
    float* cp = Cp + (size_t)blockIdx.z * M * N;
    #pragma unroll
    for (int i = 0; i < 4; i++){
        int m = m0 + tr*4 + i;
        #pragma unroll
        for (int j = 0; j < 4; j++){
            int n = n0 + tc*4 + j;
            if (n < N) cp[(size_t)m*N + n] = acc[i][j];
        }
    }
}

// ---- staging: reduce 4 split-K partials + bias + relu into shared [8][HID] ----
__device__ __forceinline__ void stage_act(float (*As)[HID], const float* __restrict__ Cp,
                                          const float* __restrict__ bias, int m0, int tid){
    for (int t = tid; t < 8*(HID/4); t += 256){
        int r = t >> 7, k4 = t & 127;
        float4 v = ((const float4*)bias)[k4];
        #pragma unroll
        for (int z = 0; z < 4; z++){
            float4 p = ((const float4*)(Cp + (size_t)z*B*HID + (size_t)(m0+r)*HID))[k4];
            v.x+=p.x; v.y+=p.y; v.z+=p.z; v.w+=p.w;
        }
        ((float4*)As[r])[k4] = make_float4(fmaxf(v.x,0.f),fmaxf(v.y,0.f),
                                           fmaxf(v.z,0.f),fmaxf(v.w,0.f));
    }
}

// ---------------- K_mulv: warp-per-row, lane-split-K; grid (32,2) ----------------
__global__ __launch_bounds__(256) void k_mulv(const float* __restrict__ Cp,
        const float* __restrict__ b_enc,
        const float* __restrict__ W_mu, const float* __restrict__ b_mu,
        const float* __restrict__ W_lv, const float* __restrict__ b_lv,
        const float* __restrict__ eps, float* __restrict__ out){
    __shared__ __align__(16) float As[8][HID];
    int m0 = blockIdx.x * 8;
    int tid = threadIdx.x;
    stage_act(As, Cp, b_enc, m0, tid);
    __syncthreads();
    int w = tid >> 5, l = tid & 31;
    int m = m0 + w;
    const float4* ar = (const float4*)As[w];
    int cbase = blockIdx.y * 32;
    #pragma unroll 1
    for (int pp = 0; pp < 16; pp++){
        int cc = cbase + 2*pp;
        float am0=0.f, am1=0.f, al0=0.f, al1=0.f;
        const float4* wm0 = (const float4*)(W_mu + (size_t)cc*HID);
        const float4* wm1 = (const float4*)(W_mu + (size_t)(cc+1)*HID);
        const float4* wl0 = (const float4*)(W_lv + (size_t)cc*HID);
        const float4* wl1 = (const float4*)(W_lv + (size_t)(cc+1)*HID);
        #pragma unroll
        for (int i = 0; i < 4; i++){
            int k4 = i*32 + l;
            float4 a  = ar[k4];
            float4 m4 = wm0[k4], n4 = wm1[k4], u4 = wl0[k4], v4 = wl1[k4];
            am0=fmaf(a.x,m4.x,am0); am0=fmaf(a.y,m4.y,am0); am0=fmaf(a.z,m4.z,am0); am0=fmaf(a.w,m4.w,am0);
            am1=fmaf(a.x,n4.x,am1); am1=fmaf(a.y,n4.y,am1); am1=fmaf(a.z,n4.z,am1); am1=fmaf(a.w,n4.w,am1);
            al0=fmaf(a.x,u4.x,al0); al0=fmaf(a.y,u4.y,al0); al0=fmaf(a.z,u4.z,al0); al0=fmaf(a.w,u4.w,al0);
            al1=fmaf(a.x,v4.x,al1); al1=fmaf(a.y,v4.y,al1); al1=fmaf(a.z,v4.z,al1); al1=fmaf(a.w,v4.w,al1);
        }
        #pragma unroll
        for (int o = 16; o > 0; o >>= 1){
            am0 += __shfl_down_sync(0xffffffffu, am0, o);
            am1 += __shfl_down_sync(0xffffffffu, am1, o);
            al0 += __shfl_down_sync(0xffffffffu, al0, o);
            al1 += __shfl_down_sync(0xffffffffu, al1, o);
        }
        if (l == 0){
            float mu0 = am0 + b_mu[cc],   lv0 = al0 + b_lv[cc];
            float mu1 = am1 + b_mu[cc+1], lv1 = al1 + b_lv[cc+1];
            out[OUT_ZM + m*LAT + cc]   = mu0;
            out[OUT_ZM + m*LAT + cc+1] = mu1;
            out[OUT_LV + m*LAT + cc]   = lv0;
            out[OUT_LV + m*LAT + cc+1] = lv1;
            g_dz[(size_t)m*IN_DEC + cc]   = mu0 + eps[m*LAT + cc]   * expf(0.5f*lv0);
            g_dz[(size_t)m*IN_DEC + cc+1] = mu1 + eps[m*LAT + cc+1] * expf(0.5f*lv1);
        }
    }
}

// ---------------- K_d2: warp-per-row, lane-split-K -> rx; grid (32,2) ----------------
__global__ __launch_bounds__(256) void k_d2(const float* __restrict__ Cp,
        const float* __restrict__ b_d1,
        const float* __restrict__ W_d2, const float* __restrict__ b_d2){
    __shared__ __align__(16) float As[8][HID];
    int m0 = blockIdx.x * 8;
    int tid = threadIdx.x;
    stage_act(As, Cp, b_d1, m0, tid);
    __syncthreads();
    int w = tid >> 5, l = tid & 31;
    int m = m0 + w;
    const float4* ar = (const float4*)As[w];
    int cbase = blockIdx.y * 80;
    #pragma unroll 1
    for (int pp = 0; pp < 40; pp++){
        int cc = cbase + 2*pp;
        float a0 = 0.f, a1 = 0.f;
        const float4* w0 = (const float4*)(W_d2 + (size_t)cc*HID);
        const float4* w1 = (const float4*)(W_d2 + (size_t)(cc+1)*HID);
        #pragma unroll
        for (int i = 0; i < 4; i++){
            int k4 = i*32 + l;
            float4 a  = ar[k4];
            float4 x0 = w0[k4], x1 = w1[k4];
            a0=fmaf(a.x,x0.x,a0); a0=fmaf(a.y,x0.y,a0); a0=fmaf(a.z,x0.z,a0); a0=fmaf(a.w,x0.w,a0);
            a1=fmaf(a.x,x1.x,a1); a1=fmaf(a.y,x1.y,a1); a1=fmaf(a.z,x1.z,a1); a1=fmaf(a.w,x1.w,a1);
        }
        #pragma unroll
        for (int o = 16; o > 0; o >>= 1){
            a0 += __shfl_down_sync(0xffffffffu, a0, o);
            a1 += __shfl_down_sync(0xffffffffu, a1, o);
        }
        if (l == 0){
            g_rx[(size_t)m*KE + cc]   = fmaxf(a0 + b_d2[cc],   0.f);
            g_rx[(size_t)m*KE + cc+1] = fmaxf(a1 + b_d2[cc+1], 0.f);
        }
    }
}

// ---------------- K_score v4: item-pair f32x2, single chain, deferred argmax ----------------
__global__ __launch_bounds__(256,2) void k_score(const float* __restrict__ emb){
    __shared__ __align__(16) float sh[SUBT * E];
    int c = blockIdx.x;
    int tid = threadIdx.x;
    int r0 = blockIdx.y * 512 + tid;
    int r1 = r0 + 256;

    ull rxa[E], rxb[E];
    #pragma unroll
    for (int e = 0; e < E; e++){
        rxa[e] = dup2(g_rx[(size_t)r0*E + e] * LOG2E);
        rxb[e] = dup2(g_rx[(size_t)r1*E + e] * LOG2E);
    }
    float m0v = -INFINITY, s0 = 0.f, m1v = -INFINITY, s1 = 0.f;
    int n0 = c * CHUNK;

    for (int t0 = 0; t0 < CHUNK; t0 += SUBT){
        __syncthreads();
        if (tid < SUBT){
            int n = n0 + t0 + tid;
            const float4* e4 = (const float4*)(emb + (size_t)n * E);
            float* dst = sh + (tid >> 1) * 32 + (tid & 1);
            #pragma unroll
            for (int q = 0; q < 4; q++){
                float4 v = e4[q];
                dst[(4*q+0)*2] = v.x; dst[(4*q+1)*2] = v.y;
                dst[(4*q+2)*2] = v.z; dst[(4*q+3)*2] = v.w;
            }
        }
        __syncthreads();
        const ulonglong2* s2 = (const ulonglong2*)sh;
        #pragma unroll 1
        for (int p = 0; p < SUBT/2; p++){
            ull a0 = 0ull, a1 = 0ull;
            #pragma unroll
            for (int e2 = 0; e2 < 8; e2++){
                ulonglong2 w = s2[p*8 + e2];
                asm("fma.rn.f32x2 %0, %1, %2, %0;" : "+l"(a0) : "l"(w.x), "l"(rxa[2*e2]));
                asm("fma.rn.f32x2 %0, %1, %2, %0;" : "+l"(a0) : "l"(w.y), "l"(rxa[2*e2+1]));
                asm("fma.rn.f32x2 %0, %1, %2, %0;" : "+l"(a1) : "l"(w.x), "l"(rxb[2*e2]));
                asm("fma.rn.f32x2 %0, %1, %2, %0;" : "+l"(a1) : "l"(w.y), "l"(rxb[2*e2+1]));
            }
            float l0 = p_lo(a0), l1 = p_hi(a0);
            float l2 = p_lo(a1), l3 = p_hi(a1);
            s0 += ex2f(l0);  m0v = fmaxf(m0v, l0);
            s0 += ex2f(l1);  m0v = fmaxf(m0v, l1);
            s1 += ex2f(l2);  m1v = fmaxf(m1v, l2);
            s1 += ex2f(l3);  m1v = fmaxf(m1v, l3);
        }
    }
    g_pmax[c*ROWS + r0] = m0v; g_psum[c*ROWS + r0] = s0;
    g_pmax[c*ROWS + r1] = m1v; g_psum[c*ROWS + r1] = s1;
}

// ---------------- K_final: combine chunk partials; winning chunk + resp ----------------
__global__ void k_final(const float* __restrict__ emb, const int* __restrict__ slate,
                        float* __restrict__ out){
    int r = blockIdx.x * 256 + threadIdx.x;
    float M = -INFINITY, T = 0.f;
    int wc = 0;
    #pragma unroll 1
    for (int c = 0; c < NCH; c++){
        float pm = g_pmax[c*ROWS + r];
        if (pm > M){ M = pm; wc = c; }
        T += g_psum[c*ROWS + r];
    }
    g_winc[r] = wc;
    g_wmax[r] = M;
    int ns = slate[r];
    const float* er = emb + (size_t)ns * E;
    const float* rr = g_rx + (size_t)r * E;
    float dot = 0.f;
    #pragma unroll
    for (int e = 0; e < E; e++) dot += rr[e] * er[e];
    out[OUT_RP + r] = ex2f(dot * LOG2E) / T;
}

// ---------------- K_rec: recover argmax index via exact scalar replay ----------------
__global__ __launch_bounds__(256) void k_rec(const float* __restrict__ emb,
                                             float* __restrict__ out){
    int w = threadIdx.x >> 5, lane = threadIdx.x & 31;
    int r = blockIdx.x * 8 + w;
    int c = g_winc[r];
    float M = g_wmax[r];
    float rxs[E];
    const float* rr = g_rx + (size_t)r * E;
    #pragma unroll
    for (int e = 0; e < E; e++) rxs[e] = rr[e] * LOG2E;
    int base = c * CHUNK;
    int best = 0x7fffffff;
    #pragma unroll 1
    for (int it = 0; it < (CHUNK + 31)/32; it++){
        int n = base + it*32 + lane;
        float lv = -INFINITY;
        if (n < base + CHUNK){
            const float4* ep = (const float4*)(emb + (size_t)n * E);
            float acc = 0.f;
            #pragma unroll
            for (int q = 0; q < 4; q++){
                float4 v = ep[q];
                acc = fmaf(v.x, rxs[4*q+0], acc);
                acc = fmaf(v.y, rxs[4*q+1], acc);
                acc = fmaf(v.z, rxs[4*q+2], acc);
                acc = fmaf(v.w, rxs[4*q+3], acc);
            }
            lv = acc;
        }
        unsigned msk = __ballot_sync(0xffffffffu, lv == M);
        if (msk && best == 0x7fffffff) best = base + it*32 + (__ffs(msk) - 1);
    }
    if (lane == 0) out[OUT_SL + r] = (float)best;
}

// ---------------- launcher ----------------
extern "C" void kernel_launch(void* const* d_in, const int* in_sizes, int n_in,
                              void* d_out, int out_size){
    const int*   ur    = (const int*)  d_in[0];
    const int*   slate = (const int*)  d_in[1];
    const float* resp  = (const float*)d_in[2];
    const float* eps   = (const float*)d_in[3];
    const float* emb   = (const float*)d_in[4];
    const float* W_enc = (const float*)d_in[5];
    const float* b_enc = (const float*)d_in[6];
    const float* W_mu  = (const float*)d_in[7];
    const float* b_mu  = (const float*)d_in[8];
    const float* W_lv  = (const float*)d_in[9];
    const float* b_lv  = (const float*)d_in[10];
    const float* W_d1  = (const float*)d_in[11];
    const float* b_d1  = (const float*)d_in[12];
    const float* W_d2  = (const float*)d_in[13];
    const float* b_d2  = (const float*)d_in[14];
    float* out = (float*)d_out;

    void *px, *pdz, *pp;
    cudaGetSymbolAddress(&px,  g_x);
    cudaGetSymbolAddress(&pdz, g_dz);
    cudaGetSymbolAddress(&pp,  g_part);

    cudaFuncSetAttribute(k_pool, cudaFuncAttributeMaxDynamicSharedMemorySize, SMEM_POOL);

    k_pool<<<dim3(NIC,16), 256, SMEM_POOL>>>(ur, emb);                                   // 0
    k_build<<<B, 256>>>(slate, resp, emb);                                               // 1
    sgemm_part<<<dim3(4,8,4), 256>>>((const float*)px, W_enc, (float*)pp, B, HID, IN_ENC, 304); // 2
    // DIAGNOSTIC at capture slot 3: FULL-SIZE duplicate k_score on stale-but-
    // deterministic g_rx (zeros on first pass, prior-replay values after).
    // Outputs fully overwritten by the real k_score at launch 7 -> harmless.
    k_score<<<dim3(NCH, ROWS/512), 256>>>(emb);                                          // 3 <- ncu slot
    k_mulv<<<dim3(32,2), 256>>>((const float*)pp, b_enc, W_mu, b_mu, W_lv, b_lv, eps, out);     // 4
    sgemm_part<<<dim3(4,8,4), 256>>>((const float*)pdz, W_d1, (float*)pp, B, HID, IN_DEC, 288); // 5
    k_d2<<<dim3(32,2), 256>>>((const float*)pp, b_d1, W_d2, b_d2);                       // 6
    k_score<<<dim3(NCH, ROWS/512), 256>>>(emb);                                          // 7
    k_final<<<ROWS/256, 256>>>(emb, slate, out);                                         // 8
    k_rec<<<ROWS/8, 256>>>(emb, out);                                                    // 9
}

// round 14
// speedup vs baseline: 1.3889x; 1.3889x over previous
#include <cuda_runtime.h>
#include <math.h>

// ---------------- problem dims ----------------
#define B     256
#define NIT   50000
#define E     16
#define SL    10
#define HID   512
#define LAT   64
#define RESPD 1024
#define IN_ENC 1200
#define IN_DEC 1104
#define KE    160
#define ROWS  2560

#define NCH   100
#define CHUNK 500
#define SUBT  250
#define LOG2E 1.4426950408889634f

// pooling tiling: IC=512 -> 65.7KB smem -> 3 blocks/SM
#define IC    512
#define NIC   98
#define UPAD  514
#define SMEM_POOL ((IC*E + 16*UPAD)*4)   // 65664 B

// output layout (float32)
#define OUT_ZM 0
#define OUT_LV 16384
#define OUT_SL 32768
#define OUT_RP 35328

typedef unsigned long long ull;

// ---------------- device scratch ----------------
__device__ float g_x [B*IN_ENC];
__device__ float g_dz[B*IN_DEC];
__device__ float g_rx[B*KE];
__device__ float g_part[4*B*HID];
__device__ float g_upart[NIC*B*17];
__device__ float g_pmax[NCH*ROWS];
__device__ float g_psum[NCH*ROWS];
__device__ int   g_winc[ROWS];
__device__ float g_wmax[ROWS];

__device__ __forceinline__ float ex2f(float x){
    float y; asm("ex2.approx.f32 %0, %1;" : "=f"(y) : "f"(x)); return y;
}
__device__ __forceinline__ float p_lo(ull a){
    return __uint_as_float((unsigned)(a & 0xffffffffull));
}
__device__ __forceinline__ float p_hi(ull a){
    return __uint_as_float((unsigned)(a >> 32));
}
__device__ __forceinline__ ull dup2(float v){
    unsigned u = __float_as_uint(v);
    return (ull)u | ((ull)u << 32);
}

// ---------------- K1: dense pooling partials = (indicator @ emb) via f32x2 ----------------
__global__ __launch_bounds__(256,3) void k_pool(const int* __restrict__ ur,
                                                const float* __restrict__ emb){
    extern __shared__ float sm[];
    float* sh_e = sm;              // IC*16 floats, item-pair interleaved
    float* s_u  = sm + IC*E;       // 16*UPAD floats
    int tid = threadIdx.x;
    int c = blockIdx.x, bg = blockIdx.y;
    int n0 = c*IC;

    for (int t = tid; t < IC*4; t += 256){
        int i = t >> 2, q = t & 3;
        int n = n0 + i;
        float4 v = make_float4(0.f,0.f,0.f,0.f);
        if (n < NIT) v = ((const float4*)emb)[n*4 + q];
        float* dst = sh_e + (i>>1)*32 + (i&1);
        dst[(4*q+0)*2]=v.x; dst[(4*q+1)*2]=v.y; dst[(4*q+2)*2]=v.z; dst[(4*q+3)*2]=v.w;
    }
    for (int t = tid; t < 16*(IC/4); t += 256){
        int bb = t >> 7, j = t & 127;
        int n = n0 + 4*j;
        float4 f = make_float4(0.f,0.f,0.f,0.f);
        if (n < NIT){
            int4 u = ((const int4*)ur)[((size_t)(bg*16+bb)*NIT + n) >> 2];
            f = make_float4((float)u.x,(float)u.y,(float)u.z,(float)u.w);
        }
        float* du = s_u + bb*UPAD + 4*j;
        du[0]=f.x; du[1]=f.y; du[2]=f.z; du[3]=f.w;
    }
    __syncthreads();

    int w = tid >> 5, l = tid & 31;
    int ss = w*2 + (l>>4);
    int bb = l & 15;
    ull acc[E], cnt2 = 0ull;
    #pragma unroll
    for (int e = 0; e < E; e++) acc[e] = 0ull;
    const ulonglong2* e128 = (const ulonglong2*)sh_e;
    const float* urow = s_u + bb*UPAD;
    #pragma unroll 1
    for (int k = 0; k < IC/32; k++){
        int p = ss + 16*k;
        ull u2 = *(const ull*)(urow + 2*p);
        #pragma unroll
        for (int e2 = 0; e2 < 8; e2++){
            ulonglong2 wv = e128[p*8 + e2];
            asm("fma.rn.f32x2 %0, %1, %2, %0;" : "+l"(acc[2*e2])   : "l"(wv.x), "l"(u2));
            asm("fma.rn.f32x2 %0, %1, %2, %0;" : "+l"(acc[2*e2+1]) : "l"(wv.y), "l"(u2));
        }
        asm("add.rn.f32x2 %0, %1, %2;" : "=l"(cnt2) : "l"(cnt2), "l"(u2));
    }
    __syncthreads();
    float* s_part = s_u;
    float* dst = s_part + (ss*16 + bb)*17;
    #pragma unroll
    for (int e = 0; e < E; e++) dst[e] = p_lo(acc[e]) + p_hi(acc[e]);
    dst[16] = p_lo(cnt2) + p_hi(cnt2);
    __syncthreads();
    {
        int b2 = tid >> 4, d = tid & 15;
        float v = 0.f, cv = 0.f;
        #pragma unroll 1
        for (int s2 = 0; s2 < 16; s2++){
            v  += s_part[(s2*16 + b2)*17 + d];
            cv += s_part[(s2*16 + b2)*17 + 16];
        }
        int batch = bg*16 + b2;
        g_upart[((size_t)c*B + batch)*17 + d] = v;
        if (d == 0) g_upart[((size_t)c*B + batch)*17 + 16] = cv;
    }
}

// ---------------- K2: finalize user mean, build x and dz(user/resp) ----------------
__global__ void k_build(const int* __restrict__ slate, const float* __restrict__ resp,
                        const float* __restrict__ emb){
    int b = blockIdx.x, tid = threadIdx.x;
    __shared__ float su[17];
    if (tid < 17){
        float v = 0.f;
        #pragma unroll 1
        for (int c = 0; c < NIC; c++) v += g_upart[((size_t)c*B + b)*17 + tid];
        su[tid] = v;
    }
    __syncthreads();
    float* xr  = g_x  + (size_t)b*IN_ENC;
    float* dzr = g_dz + (size_t)b*IN_DEC;
    if (tid < KE){
        int k = tid >> 4, e = tid & 15;
        xr[tid] = emb[(size_t)slate[b*SL + k]*E + e];
    } else if (tid < KE + E){
        float u = su[tid - KE] / su[16];
        xr[tid] = u;
        dzr[LAT + (tid - KE)] = u;
    }
    for (int j = tid; j < RESPD; j += 256){
        float rv = resp[(size_t)b*RESPD + j];
        xr[KE + E + j]   = rv;
        dzr[LAT + E + j] = rv;
    }
}

// ---------------- split-K fp32 SGEMM ----------------
#define GBM 64
#define GBN 64
#define GBK 16
#define GPAD 4
__global__ void sgemm_part(const float* __restrict__ A, const float* __restrict__ W,
                           float* __restrict__ Cp, int M, int N, int K, int kslice){
    __shared__ __align__(16) float As[GBK][GBM + GPAD];
    __shared__ __align__(16) float Bs[GBK][GBN + GPAD];
    int tid = threadIdx.x;
    int m0 = blockIdx.x * GBM, n0 = blockIdx.y * GBN;
    int kbeg = blockIdx.z * kslice;
    int kend = min(K, kbeg + kslice);
    int tr = tid >> 4, tc = tid & 15;
    int lr = tid >> 2, lk = (tid & 3) * 4;
    float acc[4][4];
    #pragma unroll
    for (int i = 0; i < 4; i++)
        #pragma unroll
        for (int j = 0; j < 4; j++) acc[i][j] = 0.f;

    for (int k0 = kbeg; k0 < kend; k0 += GBK){
        float4 av = *(const float4*)(A + (size_t)(m0 + lr) * K + k0 + lk);
        float4 bv = make_float4(0.f, 0.f, 0.f, 0.f);
        if (n0 + lr < N) bv = *(const float4*)(W + (size_t)(n0 + lr) * K + k0 + lk);
        __syncthreads();
        As[lk+0][lr] = av.x; As[lk+1][lr] = av.y; As[lk+2][lr] = av.z; As[lk+3][lr] = av.w;
        Bs[lk+0][lr] = bv.x; Bs[lk+1][lr] = bv.y; Bs[lk+2][lr] = bv.z; Bs[lk+3][lr] = bv.w;
        __syncthreads();
        #pragma unroll
        for (int kk = 0; kk < GBK; kk++){
            float4 a4 = *(const float4*)&As[kk][tr*4];
            float4 b4 = *(const float4*)&Bs[kk][tc*4];
            float ra[4] = {a4.x, a4.y, a4.z, a4.w};
            float rb[4] = {b4.x, b4.y, b4.z, b4.w};
            #pragma unroll
            for (int i = 0; i < 4; i++)
                #pragma unroll
                for (int j = 0; j < 4; j++)
                    acc[i][j] += ra[i] * rb[j];
        }
    }
    float* cp = Cp + (size_t)blockIdx.z * M * N;
    #pragma unroll
    for (int i = 0; i < 4; i++){
        int m = m0 + tr*4 + i;
        #pragma unroll
        for (int j = 0; j < 4; j++){
            int n = n0 + tc*4 + j;
            if (n < N) cp[(size_t)m*N + n] = acc[i][j];
        }
    }
}

// ---- staging: reduce 4 split-K partials + bias + relu into shared [8][HID] ----
__device__ __forceinline__ void stage_act(float (*As)[HID], const float* __restrict__ Cp,
                                          const float* __restrict__ bias, int m0, int tid){
    for (int t = tid; t < 8*(HID/4); t += 256){
        int r = t >> 7, k4 = t & 127;
        float4 v = ((const float4*)bias)[k4];
        #pragma unroll
        for (int z = 0; z < 4; z++){
            float4 p = ((const float4*)(Cp + (size_t)z*B*HID + (size_t)(m0+r)*HID))[k4];
            v.x+=p.x; v.y+=p.y; v.z+=p.z; v.w+=p.w;
        }
        ((float4*)As[r])[k4] = make_float4(fmaxf(v.x,0.f),fmaxf(v.y,0.f),
                                           fmaxf(v.z,0.f),fmaxf(v.w,0.f));
    }
}

// ---------------- K_mulv: warp-per-row, lane-split-K; grid (32,2) ----------------
__global__ __launch_bounds__(256) void k_mulv(const float* __restrict__ Cp,
        const float* __restrict__ b_enc,
        const float* __restrict__ W_mu, const float* __restrict__ b_mu,
        const float* __restrict__ W_lv, const float* __restrict__ b_lv,
        const float* __restrict__ eps, float* __restrict__ out){
    __shared__ __align__(16) float As[8][HID];
    int m0 = blockIdx.x * 8;
    int tid = threadIdx.x;
    stage_act(As, Cp, b_enc, m0, tid);
    __syncthreads();
    int w = tid >> 5, l = tid & 31;
    int m = m0 + w;
    const float4* ar = (const float4*)As[w];
    int cbase = blockIdx.y * 32;
    #pragma unroll 1
    for (int pp = 0; pp < 16; pp++){
        int cc = cbase + 2*pp;
        float am0=0.f, am1=0.f, al0=0.f, al1=0.f;
        const float4* wm0 = (const float4*)(W_mu + (size_t)cc*HID);
        const float4* wm1 = (const float4*)(W_mu + (size_t)(cc+1)*HID);
        const float4* wl0 = (const float4*)(W_lv + (size_t)cc*HID);
        const float4* wl1 = (const float4*)(W_lv + (size_t)(cc+1)*HID);
        #pragma unroll
        for (int i = 0; i < 4; i++){
            int k4 = i*32 + l;
            float4 a  = ar[k4];
            float4 m4 = wm0[k4], n4 = wm1[k4], u4 = wl0[k4], v4 = wl1[k4];
            am0=fmaf(a.x,m4.x,am0); am0=fmaf(a.y,m4.y,am0); am0=fmaf(a.z,m4.z,am0); am0=fmaf(a.w,m4.w,am0);
            am1=fmaf(a.x,n4.x,am1); am1=fmaf(a.y,n4.y,am1); am1=fmaf(a.z,n4.z,am1); am1=fmaf(a.w,n4.w,am1);
            al0=fmaf(a.x,u4.x,al0); al0=fmaf(a.y,u4.y,al0); al0=fmaf(a.z,u4.z,al0); al0=fmaf(a.w,u4.w,al0);
            al1=fmaf(a.x,v4.x,al1); al1=fmaf(a.y,v4.y,al1); al1=fmaf(a.z,v4.z,al1); al1=fmaf(a.w,v4.w,al1);
        }
        #pragma unroll
        for (int o = 16; o > 0; o >>= 1){
            am0 += __shfl_down_sync(0xffffffffu, am0, o);
            am1 += __shfl_down_sync(0xffffffffu, am1, o);
            al0 += __shfl_down_sync(0xffffffffu, al0, o);
            al1 += __shfl_down_sync(0xffffffffu, al1, o);
        }
        if (l == 0){
            float mu0 = am0 + b_mu[cc],   lv0 = al0 + b_lv[cc];
            float mu1 = am1 + b_mu[cc+1], lv1 = al1 + b_lv[cc+1];
            out[OUT_ZM + m*LAT + cc]   = mu0;
            out[OUT_ZM + m*LAT + cc+1] = mu1;
            out[OUT_LV + m*LAT + cc]   = lv0;
            out[OUT_LV + m*LAT + cc+1] = lv1;
            g_dz[(size_t)m*IN_DEC + cc]   = mu0 + eps[m*LAT + cc]   * expf(0.5f*lv0);
            g_dz[(size_t)m*IN_DEC + cc+1] = mu1 + eps[m*LAT + cc+1] * expf(0.5f*lv1);
        }
    }
}

// ---------------- K_d2: warp-per-row, lane-split-K -> rx; grid (32,2) ----------------
__global__ __launch_bounds__(256) void k_d2(const float* __restrict__ Cp,
        const float* __restrict__ b_d1,
        const float* __restrict__ W_d2, const float* __restrict__ b_d2){
    __shared__ __align__(16) float As[8][HID];
    int m0 = blockIdx.x * 8;
    int tid = threadIdx.x;
    stage_act(As, Cp, b_d1, m0, tid);
    __syncthreads();
    int w = tid >> 5, l = tid & 31;
    int m = m0 + w;
    const float4* ar = (const float4*)As[w];
    int cbase = blockIdx.y * 80;
    #pragma unroll 1
    for (int pp = 0; pp < 40; pp++){
        int cc = cbase + 2*pp;
        float a0 = 0.f, a1 = 0.f;
        const float4* w0 = (const float4*)(W_d2 + (size_t)cc*HID);
        const float4* w1 = (const float4*)(W_d2 + (size_t)(cc+1)*HID);
        #pragma unroll
        for (int i = 0; i < 4; i++){
            int k4 = i*32 + l;
            float4 a  = ar[k4];
            float4 x0 = w0[k4], x1 = w1[k4];
            a0=fmaf(a.x,x0.x,a0); a0=fmaf(a.y,x0.y,a0); a0=fmaf(a.z,x0.z,a0); a0=fmaf(a.w,x0.w,a0);
            a1=fmaf(a.x,x1.x,a1); a1=fmaf(a.y,x1.y,a1); a1=fmaf(a.z,x1.z,a1); a1=fmaf(a.w,x1.w,a1);
        }
        #pragma unroll
        for (int o = 16; o > 0; o >>= 1){
            a0 += __shfl_down_sync(0xffffffffu, a0, o);
            a1 += __shfl_down_sync(0xffffffffu, a1, o);
        }
        if (l == 0){
            g_rx[(size_t)m*KE + cc]   = fmaxf(a0 + b_d2[cc],   0.f);
            g_rx[(size_t)m*KE + cc+1] = fmaxf(a1 + b_d2[cc+1], 0.f);
        }
    }
}

// ---------------- K_score v5: item-pair f32x2, SPLIT chains, 3 blocks/SM ----------------
// Each row's 16-FMA2 chain split into two independent 8-FMA2 chains (dims 0-7,
// dims 8-15) merged by one add.rn.f32x2 -> 4 independent chains/warp in flight.
// k_rec replays the identical split scalar-wise -> bitwise-equal logits.
__global__ __launch_bounds__(256,3) void k_score(const float* __restrict__ emb){
    __shared__ __align__(16) float sh[SUBT * E];   // [pair][dim][item], 16000 B
    int c = blockIdx.x;
    int tid = threadIdx.x;
    int r0 = blockIdx.y * 512 + tid;
    int r1 = r0 + 256;

    ull rxa[E], rxb[E];
    #pragma unroll
    for (int e = 0; e < E; e++){
        rxa[e] = dup2(g_rx[(size_t)r0*E + e] * LOG2E);
        rxb[e] = dup2(g_rx[(size_t)r1*E + e] * LOG2E);
    }
    float m0v = -INFINITY, s0 = 0.f, m1v = -INFINITY, s1 = 0.f;
    int n0 = c * CHUNK;

    for (int t0 = 0; t0 < CHUNK; t0 += SUBT){
        __syncthreads();
        if (tid < SUBT){
            int n = n0 + t0 + tid;
            const float4* e4 = (const float4*)(emb + (size_t)n * E);
            float* dst = sh + (tid >> 1) * 32 + (tid & 1);
            #pragma unroll
            for (int q = 0; q < 4; q++){
                float4 v = e4[q];
                dst[(4*q+0)*2] = v.x; dst[(4*q+1)*2] = v.y;
                dst[(4*q+2)*2] = v.z; dst[(4*q+3)*2] = v.w;
            }
        }
        __syncthreads();
        const ulonglong2* s2 = (const ulonglong2*)sh;
        #pragma unroll 1
        for (int p = 0; p < SUBT/2; p++){
            ull a0a=0ull, a0b=0ull, a1a=0ull, a1b=0ull;   // 4 independent chains
            #pragma unroll
            for (int e2 = 0; e2 < 4; e2++){               // dims 0-7
                ulonglong2 w = s2[p*8 + e2];
                asm("fma.rn.f32x2 %0, %1, %2, %0;" : "+l"(a0a) : "l"(w.x), "l"(rxa[2*e2]));
                asm("fma.rn.f32x2 %0, %1, %2, %0;" : "+l"(a0a) : "l"(w.y), "l"(rxa[2*e2+1]));
                asm("fma.rn.f32x2 %0, %1, %2, %0;" : "+l"(a1a) : "l"(w.x), "l"(rxb[2*e2]));
                asm("fma.rn.f32x2 %0, %1, %2, %0;" : "+l"(a1a) : "l"(w.y), "l"(rxb[2*e2+1]));
            }
            #pragma unroll
            for (int e2 = 4; e2 < 8; e2++){               // dims 8-15
                ulonglong2 w = s2[p*8 + e2];
                asm("fma.rn.f32x2 %0, %1, %2, %0;" : "+l"(a0b) : "l"(w.x), "l"(rxa[2*e2]));
                asm("fma.rn.f32x2 %0, %1, %2, %0;" : "+l"(a0b) : "l"(w.y), "l"(rxa[2*e2+1]));
                asm("fma.rn.f32x2 %0, %1, %2, %0;" : "+l"(a1b) : "l"(w.x), "l"(rxb[2*e2]));
                asm("fma.rn.f32x2 %0, %1, %2, %0;" : "+l"(a1b) : "l"(w.y), "l"(rxb[2*e2+1]));
            }
            ull a0, a1;
            asm("add.rn.f32x2 %0, %1, %2;" : "=l"(a0) : "l"(a0a), "l"(a0b));
            asm("add.rn.f32x2 %0, %1, %2;" : "=l"(a1) : "l"(a1a), "l"(a1b));
            float l0 = p_lo(a0), l1 = p_hi(a0);
            float l2 = p_lo(a1), l3 = p_hi(a1);
            s0 += ex2f(l0);  m0v = fmaxf(m0v, l0);
            s0 += ex2f(l1);  m0v = fmaxf(m0v, l1);
            s1 += ex2f(l2);  m1v = fmaxf(m1v, l2);
            s1 += ex2f(l3);  m1v = fmaxf(m1v, l3);
        }
    }
    g_pmax[c*ROWS + r0] = m0v; g_psum[c*ROWS + r0] = s0;
    g_pmax[c*ROWS + r1] = m1v; g_psum[c*ROWS + r1] = s1;
}

// ---------------- K_final: combine chunk partials; winning chunk + resp ----------------
__global__ void k_final(const float* __restrict__ emb, const int* __restrict__ slate,
                        float* __restrict__ out){
    int r = blockIdx.x * 256 + threadIdx.x;
    float M = -INFINITY, T = 0.f;
    int wc = 0;
    #pragma unroll 1
    for (int c = 0; c < NCH; c++){
        float pm = g_pmax[c*ROWS + r];
        if (pm > M){ M = pm; wc = c; }
        T += g_psum[c*ROWS + r];
    }
    g_winc[r] = wc;
    g_wmax[r] = M;
    int ns = slate[r];
    const float* er = emb + (size_t)ns * E;
    const float* rr = g_rx + (size_t)r * E;
    float dot = 0.f;
    #pragma unroll
    for (int e = 0; e < E; e++) dot += rr[e] * er[e];
    out[OUT_RP + r] = ex2f(dot * LOG2E) / T;
}

// ---------------- K_rec: recover argmax index via exact split-chain replay ----------------
// Scalar replay: chain A = dims 0-7, chain B = dims 8-15, logit = A + B.
// Identical per-lane arithmetic to k_score v5 -> bitwise-equal.
__global__ __launch_bounds__(256) void k_rec(const float* __restrict__ emb,
                                             float* __restrict__ out){
    int w = threadIdx.x >> 5, lane = threadIdx.x & 31;
    int r = blockIdx.x * 8 + w;
    int c = g_winc[r];
    float M = g_wmax[r];
    float rxs[E];
    const float* rr = g_rx + (size_t)r * E;
    #pragma unroll
    for (int e = 0; e < E; e++) rxs[e] = rr[e] * LOG2E;
    int base = c * CHUNK;
    int best = 0x7fffffff;
    #pragma unroll 1
    for (int it = 0; it < (CHUNK + 31)/32; it++){
        int n = base + it*32 + lane;
        float lv = -INFINITY;
        if (n < base + CHUNK){
            const float4* ep = (const float4*)(emb + (size_t)n * E);
            float accA = 0.f, accB = 0.f;
            #pragma unroll
            for (int q = 0; q < 2; q++){        // dims 0-7
                float4 v = ep[q];
                accA = fmaf(v.x, rxs[4*q+0], accA);
                accA = fmaf(v.y, rxs[4*q+1], accA);
                accA = fmaf(v.z, rxs[4*q+2], accA);
                accA = fmaf(v.w, rxs[4*q+3], accA);
            }
            #pragma unroll
            for (int q = 2; q < 4; q++){        // dims 8-15
                float4 v = ep[q];
                accB = fmaf(v.x, rxs[4*q+0], accB);
                accB = fmaf(v.y, rxs[4*q+1], accB);
                accB = fmaf(v.z, rxs[4*q+2], accB);
                accB = fmaf(v.w, rxs[4*q+3], accB);
            }
            lv = accA + accB;
        }
        unsigned msk = __ballot_sync(0xffffffffu, lv == M);
        if (msk && best == 0x7fffffff) best = base + it*32 + (__ffs(msk) - 1);
    }
    if (lane == 0) out[OUT_SL + r] = (float)best;
}

// ---------------- launcher ----------------
extern "C" void kernel_launch(void* const* d_in, const int* in_sizes, int n_in,
                              void* d_out, int out_size){
    const int*   ur    = (const int*)  d_in[0];
    const int*   slate = (const int*)  d_in[1];
    const float* resp  = (const float*)d_in[2];
    const float* eps   = (const float*)d_in[3];
    const float* emb   = (const float*)d_in[4];
    const float* W_enc = (const float*)d_in[5];
    const float* b_enc = (const float*)d_in[6];
    const float* W_mu  = (const float*)d_in[7];
    const float* b_mu  = (const float*)d_in[8];
    const float* W_lv  = (const float*)d_in[9];
    const float* b_lv  = (const float*)d_in[10];
    const float* W_d1  = (const float*)d_in[11];
    const float* b_d1  = (const float*)d_in[12];
    const float* W_d2  = (const float*)d_in[13];
    const float* b_d2  = (const float*)d_in[14];
    float* out = (float*)d_out;

    void *px, *pdz, *pp;
    cudaGetSymbolAddress(&px,  g_x);
    cudaGetSymbolAddress(&pdz, g_dz);
    cudaGetSymbolAddress(&pp,  g_part);

    cudaFuncSetAttribute(k_pool, cudaFuncAttributeMaxDynamicSharedMemorySize, SMEM_POOL);

    k_pool<<<dim3(NIC,16), 256, SMEM_POOL>>>(ur, emb);                                   // 0
    k_build<<<B, 256>>>(slate, resp, emb);                                               // 1
    sgemm_part<<<dim3(4,8,4), 256>>>((const float*)px, W_enc, (float*)pp, B, HID, IN_ENC, 304); // 2
    k_mulv<<<dim3(32,2), 256>>>((const float*)pp, b_enc, W_mu, b_mu, W_lv, b_lv, eps, out);     // 3
    sgemm_part<<<dim3(4,8,4), 256>>>((const float*)pdz, W_d1, (float*)pp, B, HID, IN_DEC, 288); // 4
    k_d2<<<dim3(32,2), 256>>>((const float*)pp, b_d1, W_d2, b_d2);                       // 5
    k_score<<<dim3(NCH, ROWS/512), 256>>>(emb);                                          // 6
    k_final<<<ROWS/256, 256>>>(emb, slate, out);                                         // 7
    k_rec<<<ROWS/8, 256>>>(emb, out);                                                    // 8
}

// round 15
// speedup vs baseline: 1.6089x; 1.1584x over previous
#include <cuda_runtime.h>
#include <math.h>

// ---------------- problem dims ----------------
#define B     256
#define NIT   50000
#define E     16
#define SL    10
#define HID   512
#define LAT   64
#define RESPD 1024
#define IN_ENC 1200
#define IN_DEC 1104
#define KE    160
#define ROWS  2560

#define NCH   100
#define CHUNK 500
#define SUBT  250
#define LOG2E 1.4426950408889634f

// pooling tiling: IC=512 -> 65.7KB smem -> 3 blocks/SM
#define IC    512
#define NIC   98
#define UPAD  514
#define SMEM_POOL ((IC*E + 16*UPAD)*4)   // 65664 B

// output layout (float32)
#define OUT_ZM 0
#define OUT_LV 16384
#define OUT_SL 32768
#define OUT_RP 35328

typedef unsigned long long ull;

// ---------------- device scratch ----------------
__device__ float g_x [B*IN_ENC];
__device__ float g_dz[B*IN_DEC];
__device__ float g_rx[B*KE];
__device__ float g_part[4*B*HID];
__device__ float g_upart[NIC*B*17];
__device__ float g_pmax[NCH*ROWS];
__device__ float g_psum[NCH*ROWS];
__device__ int   g_winc[ROWS];
__device__ float g_wmax[ROWS];

__device__ __forceinline__ float ex2f(float x){
    float y; asm("ex2.approx.f32 %0, %1;" : "=f"(y) : "f"(x)); return y;
}
__device__ __forceinline__ float p_lo(ull a){
    return __uint_as_float((unsigned)(a & 0xffffffffull));
}
__device__ __forceinline__ float p_hi(ull a){
    return __uint_as_float((unsigned)(a >> 32));
}
__device__ __forceinline__ ull dup2(float v){
    unsigned u = __float_as_uint(v);
    return (ull)u | ((ull)u << 32);
}

// ---------------- K1: dense pooling partials = (indicator @ emb) via f32x2 ----------------
__global__ __launch_bounds__(256,3) void k_pool(const int* __restrict__ ur,
                                                const float* __restrict__ emb){
    extern __shared__ float sm[];
    float* sh_e = sm;              // IC*16 floats, item-pair interleaved
    float* s_u  = sm + IC*E;       // 16*UPAD floats
    int tid = threadIdx.x;
    int c = blockIdx.x, bg = blockIdx.y;
    int n0 = c*IC;

    for (int t = tid; t < IC*4; t += 256){
        int i = t >> 2, q = t & 3;
        int n = n0 + i;
        float4 v = make_float4(0.f,0.f,0.f,0.f);
        if (n < NIT) v = ((const float4*)emb)[n*4 + q];
        float* dst = sh_e + (i>>1)*32 + (i&1);
        dst[(4*q+0)*2]=v.x; dst[(4*q+1)*2]=v.y; dst[(4*q+2)*2]=v.z; dst[(4*q+3)*2]=v.w;
    }
    for (int t = tid; t < 16*(IC/4); t += 256){
        int bb = t >> 7, j = t & 127;
        int n = n0 + 4*j;
        float4 f = make_float4(0.f,0.f,0.f,0.f);
        if (n < NIT){
            int4 u = ((const int4*)ur)[((size_t)(bg*16+bb)*NIT + n) >> 2];
            f = make_float4((float)u.x,(float)u.y,(float)u.z,(float)u.w);
        }
        float* du = s_u + bb*UPAD + 4*j;
        du[0]=f.x; du[1]=f.y; du[2]=f.z; du[3]=f.w;
    }
    __syncthreads();

    int w = tid >> 5, l = tid & 31;
    int ss = w*2 + (l>>4);
    int bb = l & 15;
    ull acc[E], cnt2 = 0ull;
    #pragma unroll
    for (int e = 0; e < E; e++) acc[e] = 0ull;
    const ulonglong2* e128 = (const ulonglong2*)sh_e;
    const float* urow = s_u + bb*UPAD;
    #pragma unroll 1
    for (int k = 0; k < IC/32; k++){
        int p = ss + 16*k;
        ull u2 = *(const ull*)(urow + 2*p);
        #pragma unroll
        for (int e2 = 0; e2 < 8; e2++){
            ulonglong2 wv = e128[p*8 + e2];
            asm("fma.rn.f32x2 %0, %1, %2, %0;" : "+l"(acc[2*e2])   : "l"(wv.x), "l"(u2));
            asm("fma.rn.f32x2 %0, %1, %2, %0;" : "+l"(acc[2*e2+1]) : "l"(wv.y), "l"(u2));
        }
        asm("add.rn.f32x2 %0, %1, %2;" : "=l"(cnt2) : "l"(cnt2), "l"(u2));
    }
    __syncthreads();
    float* s_part = s_u;
    float* dst = s_part + (ss*16 + bb)*17;
    #pragma unroll
    for (int e = 0; e < E; e++) dst[e] = p_lo(acc[e]) + p_hi(acc[e]);
    dst[16] = p_lo(cnt2) + p_hi(cnt2);
    __syncthreads();
    {
        int b2 = tid >> 4, d = tid & 15;
        float v = 0.f, cv = 0.f;
        #pragma unroll 1
        for (int s2 = 0; s2 < 16; s2++){
            v  += s_part[(s2*16 + b2)*17 + d];
            cv += s_part[(s2*16 + b2)*17 + 16];
        }
        int batch = bg*16 + b2;
        g_upart[((size_t)c*B + batch)*17 + d] = v;
        if (d == 0) g_upart[((size_t)c*B + batch)*17 + 16] = cv;
    }
}

// ---------------- K2: finalize user mean, build x and dz(user/resp) ----------------
__global__ void k_build(const int* __restrict__ slate, const float* __restrict__ resp,
                        const float* __restrict__ emb){
    int b = blockIdx.x, tid = threadIdx.x;
    __shared__ float su[17];
    if (tid < 17){
        float v = 0.f;
        #pragma unroll 1
        for (int c = 0; c < NIC; c++) v += g_upart[((size_t)c*B + b)*17 + tid];
        su[tid] = v;
    }
    __syncthreads();
    float* xr  = g_x  + (size_t)b*IN_ENC;
    float* dzr = g_dz + (size_t)b*IN_DEC;
    if (tid < KE){
        int k = tid >> 4, e = tid & 15;
        xr[tid] = emb[(size_t)slate[b*SL + k]*E + e];
    } else if (tid < KE + E){
        float u = su[tid - KE] / su[16];
        xr[tid] = u;
        dzr[LAT + (tid - KE)] = u;
    }
    for (int j = tid; j < RESPD; j += 256){
        float rv = resp[(size_t)b*RESPD + j];
        xr[KE + E + j]   = rv;
        dzr[LAT + E + j] = rv;
    }
}

// ---------------- split-K fp32 SGEMM ----------------
#define GBM 64
#define GBN 64
#define GBK 16
#define GPAD 4
__global__ void sgemm_part(const float* __restrict__ A, const float* __restrict__ W,
                           float* __restrict__ Cp, int M, int N, int K, int kslice){
    __shared__ __align__(16) float As[GBK][GBM + GPAD];
    __shared__ __align__(16) float Bs[GBK][GBN + GPAD];
    int tid = threadIdx.x;
    int m0 = blockIdx.x * GBM, n0 = blockIdx.y * GBN;
    int kbeg = blockIdx.z * kslice;
    int kend = min(K, kbeg + kslice);
    int tr = tid >> 4, tc = tid & 15;
    int lr = tid >> 2, lk = (tid & 3) * 4;
    float acc[4][4];
    #pragma unroll
    for (int i = 0; i < 4; i++)
        #pragma unroll
        for (int j = 0; j < 4; j++) acc[i][j] = 0.f;

    for (int k0 = kbeg; k0 < kend; k0 += GBK){
        float4 av = *(const float4*)(A + (size_t)(m0 + lr) * K + k0 + lk);
        float4 bv = make_float4(0.f, 0.f, 0.f, 0.f);
        if (n0 + lr < N) bv = *(const float4*)(W + (size_t)(n0 + lr) * K + k0 + lk);
        __syncthreads();
        As[lk+0][lr] = av.x; As[lk+1][lr] = av.y; As[lk+2][lr] = av.z; As[lk+3][lr] = av.w;
        Bs[lk+0][lr] = bv.x; Bs[lk+1][lr] = bv.y; Bs[lk+2][lr] = bv.z; Bs[lk+3][lr] = bv.w;
        __syncthreads();
        #pragma unroll
        for (int kk = 0; kk < GBK; kk++){
            float4 a4 = *(const float4*)&As[kk][tr*4];
            float4 b4 = *(const float4*)&Bs[kk][tc*4];
            float ra[4] = {a4.x, a4.y, a4.z, a4.w};
            float rb[4] = {b4.x, b4.y, b4.z, b4.w};
            #pragma unroll
            for (int i = 0; i < 4; i++)
                #pragma unroll
                for (int j = 0; j < 4; j++)
                    acc[i][j] += ra[i] * rb[j];
        }
    }
    float* cp = Cp + (size_t)blockIdx.z * M * N;
    #pragma unroll
    for (int i = 0; i < 4; i++){
        int m = m0 + tr*4 + i;
        #pragma unroll
        for (int j = 0; j < 4; j++){
            int n = n0 + tc*4 + j;
            if (n < N) cp[(size_t)m*N + n] = acc[i][j];
        }
    }
}

// ---- staging: reduce 4 split-K partials + bias + relu into shared [4][HID] ----
__device__ __forceinline__ void stage_act4(float (*As)[HID], const float* __restrict__ Cp,
                                           const float* __restrict__ bias, int m0, int tid){
    for (int t = tid; t < 4*(HID/4); t += 256){
        int r = t >> 7, k4 = t & 127;
        float4 v = ((const float4*)bias)[k4];
        #pragma unroll
        for (int z = 0; z < 4; z++){
            float4 p = ((const float4*)(Cp + (size_t)z*B*HID + (size_t)(m0+r)*HID))[k4];
            v.x+=p.x; v.y+=p.y; v.z+=p.z; v.w+=p.w;
        }
        ((float4*)As[r])[k4] = make_float4(fmaxf(v.x,0.f),fmaxf(v.y,0.f),
                                           fmaxf(v.z,0.f),fmaxf(v.w,0.f));
    }
}

// ---------------- K_mulv: grid (64,4)=256 blocks; 4 rows x 16 cols per block ----------------
// warp w: row = w&3, col-half = w>>2 (8 cols each); 4 col-pair iterations/warp.
__global__ __launch_bounds__(256) void k_mulv(const float* __restrict__ Cp,
        const float* __restrict__ b_enc,
        const float* __restrict__ W_mu, const float* __restrict__ b_mu,
        const float* __restrict__ W_lv, const float* __restrict__ b_lv,
        const float* __restrict__ eps, float* __restrict__ out){
    __shared__ __align__(16) float As[4][HID];
    int m0 = blockIdx.x * 4;
    int tid = threadIdx.x;
    stage_act4(As, Cp, b_enc, m0, tid);
    __syncthreads();
    int w = tid >> 5, l = tid & 31;
    int r = w & 3, h = w >> 2;
    int m = m0 + r;
    const float4* ar = (const float4*)As[r];
    int cbase = blockIdx.y * 16 + h * 8;
    #pragma unroll 1
    for (int pp = 0; pp < 4; pp++){
        int cc = cbase + 2*pp;
        float am0=0.f, am1=0.f, al0=0.f, al1=0.f;
        const float4* wm0 = (const float4*)(W_mu + (size_t)cc*HID);
        const float4* wm1 = (const float4*)(W_mu + (size_t)(cc+1)*HID);
        const float4* wl0 = (const float4*)(W_lv + (size_t)cc*HID);
        const float4* wl1 = (const float4*)(W_lv + (size_t)(cc+1)*HID);
        #pragma unroll
        for (int i = 0; i < 4; i++){
            int k4 = i*32 + l;
            float4 a  = ar[k4];
            float4 m4 = wm0[k4], n4 = wm1[k4], u4 = wl0[k4], v4 = wl1[k4];
            am0=fmaf(a.x,m4.x,am0); am0=fmaf(a.y,m4.y,am0); am0=fmaf(a.z,m4.z,am0); am0=fmaf(a.w,m4.w,am0);
            am1=fmaf(a.x,n4.x,am1); am1=fmaf(a.y,n4.y,am1); am1=fmaf(a.z,n4.z,am1); am1=fmaf(a.w,n4.w,am1);
            al0=fmaf(a.x,u4.x,al0); al0=fmaf(a.y,u4.y,al0); al0=fmaf(a.z,u4.z,al0); al0=fmaf(a.w,u4.w,al0);
            al1=fmaf(a.x,v4.x,al1); al1=fmaf(a.y,v4.y,al1); al1=fmaf(a.z,v4.z,al1); al1=fmaf(a.w,v4.w,al1);
        }
        #pragma unroll
        for (int o = 16; o > 0; o >>= 1){
            am0 += __shfl_down_sync(0xffffffffu, am0, o);
            am1 += __shfl_down_sync(0xffffffffu, am1, o);
            al0 += __shfl_down_sync(0xffffffffu, al0, o);
            al1 += __shfl_down_sync(0xffffffffu, al1, o);
        }
        if (l == 0){
            float mu0 = am0 + b_mu[cc],   lv0 = al0 + b_lv[cc];
            float mu1 = am1 + b_mu[cc+1], lv1 = al1 + b_lv[cc+1];
            out[OUT_ZM + m*LAT + cc]   = mu0;
            out[OUT_ZM + m*LAT + cc+1] = mu1;
            out[OUT_LV + m*LAT + cc]   = lv0;
            out[OUT_LV + m*LAT + cc+1] = lv1;
            g_dz[(size_t)m*IN_DEC + cc]   = mu0 + eps[m*LAT + cc]   * expf(0.5f*lv0);
            g_dz[(size_t)m*IN_DEC + cc+1] = mu1 + eps[m*LAT + cc+1] * expf(0.5f*lv1);
        }
    }
}

// ---------------- K_d2: grid (64,4)=256 blocks; 4 rows x 40 cols per block ----------------
// warp w: row = w&3, col-half = w>>2 (20 cols each); 10 col-pair iterations/warp.
__global__ __launch_bounds__(256) void k_d2(const float* __restrict__ Cp,
        const float* __restrict__ b_d1,
        const float* __restrict__ W_d2, const float* __restrict__ b_d2){
    __shared__ __align__(16) float As[4][HID];
    int m0 = blockIdx.x * 4;
    int tid = threadIdx.x;
    stage_act4(As, Cp, b_d1, m0, tid);
    __syncthreads();
    int w = tid >> 5, l = tid & 31;
    int r = w & 3, h = w >> 2;
    int m = m0 + r;
    const float4* ar = (const float4*)As[r];
    int cbase = blockIdx.y * 40 + h * 20;
    #pragma unroll 1
    for (int pp = 0; pp < 10; pp++){
        int cc = cbase + 2*pp;
        float a0 = 0.f, a1 = 0.f;
        const float4* w0 = (const float4*)(W_d2 + (size_t)cc*HID);
        const float4* w1 = (const float4*)(W_d2 + (size_t)(cc+1)*HID);
        #pragma unroll
        for (int i = 0; i < 4; i++){
            int k4 = i*32 + l;
            float4 a  = ar[k4];
            float4 x0 = w0[k4], x1 = w1[k4];
            a0=fmaf(a.x,x0.x,a0); a0=fmaf(a.y,x0.y,a0); a0=fmaf(a.z,x0.z,a0); a0=fmaf(a.w,x0.w,a0);
            a1=fmaf(a.x,x1.x,a1); a1=fmaf(a.y,x1.y,a1); a1=fmaf(a.z,x1.z,a1); a1=fmaf(a.w,x1.w,a1);
        }
        #pragma unroll
        for (int o = 16; o > 0; o >>= 1){
            a0 += __shfl_down_sync(0xffffffffu, a0, o);
            a1 += __shfl_down_sync(0xffffffffu, a1, o);
        }
        if (l == 0){
            g_rx[(size_t)m*KE + cc]   = fmaxf(a0 + b_d2[cc],   0.f);
            g_rx[(size_t)m*KE + cc+1] = fmaxf(a1 + b_d2[cc+1], 0.f);
        }
    }
}

// ---------------- K_score v6: v5 chains + unroll 2 (software pipeline LDS) ----------------
// Arithmetic identical to v5 (split 8-FMA2 chains per row, add-merge, deferred
// argmax); unroll 2 lets ptxas hoist next iteration's LDS under current FMAs.
__global__ __launch_bounds__(256,3) void k_score(const float* __restrict__ emb){
    __shared__ __align__(16) float sh[SUBT * E];   // [pair][dim][item], 16000 B
    int c = blockIdx.x;
    int tid = threadIdx.x;
    int r0 = blockIdx.y * 512 + tid;
    int r1 = r0 + 256;

    ull rxa[E], rxb[E];
    #pragma unroll
    for (int e = 0; e < E; e++){
        rxa[e] = dup2(g_rx[(size_t)r0*E + e] * LOG2E);
        rxb[e] = dup2(g_rx[(size_t)r1*E + e] * LOG2E);
    }
    float m0v = -INFINITY, s0 = 0.f, m1v = -INFINITY, s1 = 0.f;
    int n0 = c * CHUNK;

    for (int t0 = 0; t0 < CHUNK; t0 += SUBT){
        __syncthreads();
        if (tid < SUBT){
            int n = n0 + t0 + tid;
            const float4* e4 = (const float4*)(emb + (size_t)n * E);
            float* dst = sh + (tid >> 1) * 32 + (tid & 1);
            #pragma unroll
            for (int q = 0; q < 4; q++){
                float4 v = e4[q];
                dst[(4*q+0)*2] = v.x; dst[(4*q+1)*2] = v.y;
                dst[(4*q+2)*2] = v.z; dst[(4*q+3)*2] = v.w;
            }
        }
        __syncthreads();
        const ulonglong2* s2 = (const ulonglong2*)sh;
        #pragma unroll 2
        for (int p = 0; p < SUBT/2; p++){
            ull a0a=0ull, a0b=0ull, a1a=0ull, a1b=0ull;   // 4 independent chains
            #pragma unroll
            for (int e2 = 0; e2 < 4; e2++){               // dims 0-7
                ulonglong2 w = s2[p*8 + e2];
                asm("fma.rn.f32x2 %0, %1, %2, %0;" : "+l"(a0a) : "l"(w.x), "l"(rxa[2*e2]));
                asm("fma.rn.f32x2 %0, %1, %2, %0;" : "+l"(a0a) : "l"(w.y), "l"(rxa[2*e2+1]));
                asm("fma.rn.f32x2 %0, %1, %2, %0;" : "+l"(a1a) : "l"(w.x), "l"(rxb[2*e2]));
                asm("fma.rn.f32x2 %0, %1, %2, %0;" : "+l"(a1a) : "l"(w.y), "l"(rxb[2*e2+1]));
            }
            #pragma unroll
            for (int e2 = 4; e2 < 8; e2++){               // dims 8-15
                ulonglong2 w = s2[p*8 + e2];
                asm("fma.rn.f32x2 %0, %1, %2, %0;" : "+l"(a0b) : "l"(w.x), "l"(rxa[2*e2]));
                asm("fma.rn.f32x2 %0, %1, %2, %0;" : "+l"(a0b) : "l"(w.y), "l"(rxa[2*e2+1]));
                asm("fma.rn.f32x2 %0, %1, %2, %0;" : "+l"(a1b) : "l"(w.x), "l"(rxb[2*e2]));
                asm("fma.rn.f32x2 %0, %1, %2, %0;" : "+l"(a1b) : "l"(w.y), "l"(rxb[2*e2+1]));
            }
            ull a0, a1;
            asm("add.rn.f32x2 %0, %1, %2;" : "=l"(a0) : "l"(a0a), "l"(a0b));
            asm("add.rn.f32x2 %0, %1, %2;" : "=l"(a1) : "l"(a1a), "l"(a1b));
            float l0 = p_lo(a0), l1 = p_hi(a0);
            float l2 = p_lo(a1), l3 = p_hi(a1);
            s0 += ex2f(l0);  m0v = fmaxf(m0v, l0);
            s0 += ex2f(l1);  m0v = fmaxf(m0v, l1);
            s1 += ex2f(l2);  m1v = fmaxf(m1v, l2);
            s1 += ex2f(l3);  m1v = fmaxf(m1v, l3);
        }
    }
    g_pmax[c*ROWS + r0] = m0v; g_psum[c*ROWS + r0] = s0;
    g_pmax[c*ROWS + r1] = m1v; g_psum[c*ROWS + r1] = s1;
}

// ---------------- K_final: combine chunk partials; winning chunk + resp ----------------
__global__ void k_final(const float* __restrict__ emb, const int* __restrict__ slate,
                        float* __restrict__ out){
    int r = blockIdx.x * 256 + threadIdx.x;
    float M = -INFINITY, T = 0.f;
    int wc = 0;
    #pragma unroll 1
    for (int c = 0; c < NCH; c++){
        float pm = g_pmax[c*ROWS + r];
        if (pm > M){ M = pm; wc = c; }
        T += g_psum[c*ROWS + r];
    }
    g_winc[r] = wc;
    g_wmax[r] = M;
    int ns = slate[r];
    const float* er = emb + (size_t)ns * E;
    const float* rr = g_rx + (size_t)r * E;
    float dot = 0.f;
    #pragma unroll
    for (int e = 0; e < E; e++) dot += rr[e] * er[e];
    out[OUT_RP + r] = ex2f(dot * LOG2E) / T;
}

// ---------------- K_rec: recover argmax index via exact split-chain replay ----------------
__global__ __launch_bounds__(256) void k_rec(const float* __restrict__ emb,
                                             float* __restrict__ out){
    int w = threadIdx.x >> 5, lane = threadIdx.x & 31;
    int r = blockIdx.x * 8 + w;
    int c = g_winc[r];
    float M = g_wmax[r];
    float rxs[E];
    const float* rr = g_rx + (size_t)r * E;
    #pragma unroll
    for (int e = 0; e < E; e++) rxs[e] = rr[e] * LOG2E;
    int base = c * CHUNK;
    int best = 0x7fffffff;
    #pragma unroll 1
    for (int it = 0; it < (CHUNK + 31)/32; it++){
        int n = base + it*32 + lane;
        float lv = -INFINITY;
        if (n < base + CHUNK){
            const float4* ep = (const float4*)(emb + (size_t)n * E);
            float accA = 0.f, accB = 0.f;
            #pragma unroll
            for (int q = 0; q < 2; q++){        // dims 0-7
                float4 v = ep[q];
                accA = fmaf(v.x, rxs[4*q+0], accA);
                accA = fmaf(v.y, rxs[4*q+1], accA);
                accA = fmaf(v.z, rxs[4*q+2], accA);
                accA = fmaf(v.w, rxs[4*q+3], accA);
            }
            #pragma unroll
            for (int q = 2; q < 4; q++){        // dims 8-15
                float4 v = ep[q];
                accB = fmaf(v.x, rxs[4*q+0], accB);
                accB = fmaf(v.y, rxs[4*q+1], accB);
                accB = fmaf(v.z, rxs[4*q+2], accB);
                accB = fmaf(v.w, rxs[4*q+3], accB);
            }
            lv = accA + accB;
        }
        unsigned msk = __ballot_sync(0xffffffffu, lv == M);
        if (msk && best == 0x7fffffff) best = base + it*32 + (__ffs(msk) - 1);
    }
    if (lane == 0) out[OUT_SL + r] = (float)best;
}

// ---------------- launcher ----------------
extern "C" void kernel_launch(void* const* d_in, const int* in_sizes, int n_in,
                              void* d_out, int out_size){
    const int*   ur    = (const int*)  d_in[0];
    const int*   slate = (const int*)  d_in[1];
    const float* resp  = (const float*)d_in[2];
    const float* eps   = (const float*)d_in[3];
    const float* emb   = (const float*)d_in[4];
    const float* W_enc = (const float*)d_in[5];
    const float* b_enc = (const float*)d_in[6];
    const float* W_mu  = (const float*)d_in[7];
    const float* b_mu  = (const float*)d_in[8];
    const float* W_lv  = (const float*)d_in[9];
    const float* b_lv  = (const float*)d_in[10];
    const float* W_d1  = (const float*)d_in[11];
    const float* b_d1  = (const float*)d_in[12];
    const float* W_d2  = (const float*)d_in[13];
    const float* b_d2  = (const float*)d_in[14];
    float* out = (float*)d_out;

    void *px, *pdz, *pp;
    cudaGetSymbolAddress(&px,  g_x);
    cudaGetSymbolAddress(&pdz, g_dz);
    cudaGetSymbolAddress(&pp,  g_part);

    cudaFuncSetAttribute(k_pool, cudaFuncAttributeMaxDynamicSharedMemorySize, SMEM_POOL);

    k_pool<<<dim3(NIC,16), 256, SMEM_POOL>>>(ur, emb);                                   // 0
    k_build<<<B, 256>>>(slate, resp, emb);                                               // 1
    sgemm_part<<<dim3(4,8,4), 256>>>((const float*)px, W_enc, (float*)pp, B, HID, IN_ENC, 304); // 2
    k_mulv<<<dim3(64,4), 256>>>((const float*)pp, b_enc, W_mu, b_mu, W_lv, b_lv, eps, out);     // 3
    sgemm_part<<<dim3(4,8,4), 256>>>((const float*)pdz, W_d1, (float*)pp, B, HID, IN_DEC, 288); // 4
    k_d2<<<dim3(64,4), 256>>>((const float*)pp, b_d1, W_d2, b_d2);                       // 5
    k_score<<<dim3(NCH, ROWS/512), 256>>>(emb);                                          // 6
    k_final<<<ROWS/256, 256>>>(emb, slate, out);                                         // 7
    k_rec<<<ROWS/8, 256>>>(emb, out);                                                    // 8
}

// round 16
// speedup vs baseline: 1.7973x; 1.1171x over previous
#include <cuda_runtime.h>
#include <math.h>

// ---------------- problem dims ----------------
#define B     256
#define NIT   50000
#define E     16
#define SL    10
#define HID   512
#define LAT   64
#define RESPD 1024
#define IN_ENC 1200
#define IN_DEC 1104
#define KE    160
#define ROWS  2560

#define NCH   100
#define CHUNK 500
#define SUBT  250
#define LOG2E 1.4426950408889634f

// pooling tiling: IC=512 -> 65.7KB smem -> 3 blocks/SM
#define IC    512
#define NIC   98
#define UPAD  514
#define SMEM_POOL ((IC*E + 16*UPAD)*4)   // 65664 B

// output layout (float32)
#define OUT_ZM 0
#define OUT_LV 16384
#define OUT_SL 32768
#define OUT_RP 35328

typedef unsigned long long ull;

// ---------------- device scratch ----------------
__device__ float g_x [B*IN_ENC];
__device__ float g_dz[B*IN_DEC];
__device__ float g_rx[B*KE];
__device__ float g_part[4*B*HID];
__device__ float g_upart[NIC*B*17];
__device__ float g_pmax[NCH*ROWS];
__device__ float g_psum[NCH*ROWS];

__device__ __forceinline__ float ex2f(float x){
    float y; asm("ex2.approx.f32 %0, %1;" : "=f"(y) : "f"(x)); return y;
}
__device__ __forceinline__ float p_lo(ull a){
    return __uint_as_float((unsigned)(a & 0xffffffffull));
}
__device__ __forceinline__ float p_hi(ull a){
    return __uint_as_float((unsigned)(a >> 32));
}
__device__ __forceinline__ ull dup2(float v){
    unsigned u = __float_as_uint(v);
    return (ull)u | ((ull)u << 32);
}

// ---------------- K1: dense pooling partials = (indicator @ emb) via f32x2 ----------------
__global__ __launch_bounds__(256,3) void k_pool(const int* __restrict__ ur,
                                                const float* __restrict__ emb){
    extern __shared__ float sm[];
    float* sh_e = sm;              // IC*16 floats, item-pair interleaved
    float* s_u  = sm + IC*E;       // 16*UPAD floats
    int tid = threadIdx.x;
    int c = blockIdx.x, bg = blockIdx.y;
    int n0 = c*IC;

    for (int t = tid; t < IC*4; t += 256){
        int i = t >> 2, q = t & 3;
        int n = n0 + i;
        float4 v = make_float4(0.f,0.f,0.f,0.f);
        if (n < NIT) v = ((const float4*)emb)[n*4 + q];
        float* dst = sh_e + (i>>1)*32 + (i&1);
        dst[(4*q+0)*2]=v.x; dst[(4*q+1)*2]=v.y; dst[(4*q+2)*2]=v.z; dst[(4*q+3)*2]=v.w;
    }
    for (int t = tid; t < 16*(IC/4); t += 256){
        int bb = t >> 7, j = t & 127;
        int n = n0 + 4*j;
        float4 f = make_float4(0.f,0.f,0.f,0.f);
        if (n < NIT){
            int4 u = ((const int4*)ur)[((size_t)(bg*16+bb)*NIT + n) >> 2];
            f = make_float4((float)u.x,(float)u.y,(float)u.z,(float)u.w);
        }
        float* du = s_u + bb*UPAD + 4*j;
        du[0]=f.x; du[1]=f.y; du[2]=f.z; du[3]=f.w;
    }
    __syncthreads();

    int w = tid >> 5, l = tid & 31;
    int ss = w*2 + (l>>4);
    int bb = l & 15;
    ull acc[E], cnt2 = 0ull;
    #pragma unroll
    for (int e = 0; e < E; e++) acc[e] = 0ull;
    const ulonglong2* e128 = (const ulonglong2*)sh_e;
    const float* urow = s_u + bb*UPAD;
    #pragma unroll 1
    for (int k = 0; k < IC/32; k++){
        int p = ss + 16*k;
        ull u2 = *(const ull*)(urow + 2*p);
        #pragma unroll
        for (int e2 = 0; e2 < 8; e2++){
            ulonglong2 wv = e128[p*8 + e2];
            asm("fma.rn.f32x2 %0, %1, %2, %0;" : "+l"(acc[2*e2])   : "l"(wv.x), "l"(u2));
            asm("fma.rn.f32x2 %0, %1, %2, %0;" : "+l"(acc[2*e2+1]) : "l"(wv.y), "l"(u2));
        }
        asm("add.rn.f32x2 %0, %1, %2;" : "=l"(cnt2) : "l"(cnt2), "l"(u2));
    }
    __syncthreads();
    float* s_part = s_u;
    float* dst = s_part + (ss*16 + bb)*17;
    #pragma unroll
    for (int e = 0; e < E; e++) dst[e] = p_lo(acc[e]) + p_hi(acc[e]);
    dst[16] = p_lo(cnt2) + p_hi(cnt2);
    __syncthreads();
    {
        int b2 = tid >> 4, d = tid & 15;
        float v = 0.f, cv = 0.f;
        #pragma unroll 1
        for (int s2 = 0; s2 < 16; s2++){
            v  += s_part[(s2*16 + b2)*17 + d];
            cv += s_part[(s2*16 + b2)*17 + 16];
        }
        int batch = bg*16 + b2;
        g_upart[((size_t)c*B + batch)*17 + d] = v;
        if (d == 0) g_upart[((size_t)c*B + batch)*17 + 16] = cv;
    }
}

// ---------------- K2: finalize user mean, build x and dz(user/resp) ----------------
__global__ void k_build(const int* __restrict__ slate, const float* __restrict__ resp,
                        const float* __restrict__ emb){
    int b = blockIdx.x, tid = threadIdx.x;
    __shared__ float su[17];
    if (tid < 17){
        float v = 0.f;
        #pragma unroll 1
        for (int c = 0; c < NIC; c++) v += g_upart[((size_t)c*B + b)*17 + tid];
        su[tid] = v;
    }
    __syncthreads();
    float* xr  = g_x  + (size_t)b*IN_ENC;
    float* dzr = g_dz + (size_t)b*IN_DEC;
    if (tid < KE){
        int k = tid >> 4, e = tid & 15;
        xr[tid] = emb[(size_t)slate[b*SL + k]*E + e];
    } else if (tid < KE + E){
        float u = su[tid - KE] / su[16];
        xr[tid] = u;
        dzr[LAT + (tid - KE)] = u;
    }
    for (int j = tid; j < RESPD; j += 256){
        float rv = resp[(size_t)b*RESPD + j];
        xr[KE + E + j]   = rv;
        dzr[LAT + E + j] = rv;
    }
}

// ---------------- split-K fp32 SGEMM ----------------
#define GBM 64
#define GBN 64
#define GBK 16
#define GPAD 4
__global__ void sgemm_part(const float* __restrict__ A, const float* __restrict__ W,
                           float* __restrict__ Cp, int M, int N, int K, int kslice){
    __shared__ __align__(16) float As[GBK][GBM + GPAD];
    __shared__ __align__(16) float Bs[GBK][GBN + GPAD];
    int tid = threadIdx.x;
    int m0 = blockIdx.x * GBM, n0 = blockIdx.y * GBN;
    int kbeg = blockIdx.z * kslice;
    int kend = min(K, kbeg + kslice);
    int tr = tid >> 4, tc = tid & 15;
    int lr = tid >> 2, lk = (tid & 3) * 4;
    float acc[4][4];
    #pragma unroll
    for (int i = 0; i < 4; i++)
        #pragma unroll
        for (int j = 0; j < 4; j++) acc[i][j] = 0.f;

    for (int k0 = kbeg; k0 < kend; k0 += GBK){
        float4 av = *(const float4*)(A + (size_t)(m0 + lr) * K + k0 + lk);
        float4 bv = make_float4(0.f, 0.f, 0.f, 0.f);
        if (n0 + lr < N) bv = *(const float4*)(W + (size_t)(n0 + lr) * K + k0 + lk);
        __syncthreads();
        As[lk+0][lr] = av.x; As[lk+1][lr] = av.y; As[lk+2][lr] = av.z; As[lk+3][lr] = av.w;
        Bs[lk+0][lr] = bv.x; Bs[lk+1][lr] = bv.y; Bs[lk+2][lr] = bv.z; Bs[lk+3][lr] = bv.w;
        __syncthreads();
        #pragma unroll
        for (int kk = 0; kk < GBK; kk++){
            float4 a4 = *(const float4*)&As[kk][tr*4];
            float4 b4 = *(const float4*)&Bs[kk][tc*4];
            float ra[4] = {a4.x, a4.y, a4.z, a4.w};
            float rb[4] = {b4.x, b4.y, b4.z, b4.w};
            #pragma unroll
            for (int i = 0; i < 4; i++)
                #pragma unroll
                for (int j = 0; j < 4; j++)
                    acc[i][j] += ra[i] * rb[j];
        }
    }
    float* cp = Cp + (size_t)blockIdx.z * M * N;
    #pragma unroll
    for (int i = 0; i < 4; i++){
        int m = m0 + tr*4 + i;
        #pragma unroll
        for (int j = 0; j < 4; j++){
            int n = n0 + tc*4 + j;
            if (n < N) cp[(size_t)m*N + n] = acc[i][j];
        }
    }
}

// ---- staging: reduce 4 split-K partials + bias + relu into shared [4][HID] ----
__device__ __forceinline__ void stage_act4(float (*As)[HID], const float* __restrict__ Cp,
                                           const float* __restrict__ bias, int m0, int tid){
    for (int t = tid; t < 4*(HID/4); t += 256){
        int r = t >> 7, k4 = t & 127;
        float4 v = ((const float4*)bias)[k4];
        #pragma unroll
        for (int z = 0; z < 4; z++){
            float4 p = ((const float4*)(Cp + (size_t)z*B*HID + (size_t)(m0+r)*HID))[k4];
            v.x+=p.x; v.y+=p.y; v.z+=p.z; v.w+=p.w;
        }
        ((float4*)As[r])[k4] = make_float4(fmaxf(v.x,0.f),fmaxf(v.y,0.f),
                                           fmaxf(v.z,0.f),fmaxf(v.w,0.f));
    }
}

// ---------------- K_mulv: grid (64,4)=256 blocks; 4 rows x 16 cols per block ----------------
__global__ __launch_bounds__(256) void k_mulv(const float* __restrict__ Cp,
        const float* __restrict__ b_enc,
        const float* __restrict__ W_mu, const float* __restrict__ b_mu,
        const float* __restrict__ W_lv, const float* __restrict__ b_lv,
        const float* __restrict__ eps, float* __restrict__ out){
    __shared__ __align__(16) float As[4][HID];
    int m0 = blockIdx.x * 4;
    int tid = threadIdx.x;
    stage_act4(As, Cp, b_enc, m0, tid);
    __syncthreads();
    int w = tid >> 5, l = tid & 31;
    int r = w & 3, h = w >> 2;
    int m = m0 + r;
    const float4* ar = (const float4*)As[r];
    int cbase = blockIdx.y * 16 + h * 8;
    #pragma unroll 1
    for (int pp = 0; pp < 4; pp++){
        int cc = cbase + 2*pp;
        float am0=0.f, am1=0.f, al0=0.f, al1=0.f;
        const float4* wm0 = (const float4*)(W_mu + (size_t)cc*HID);
        const float4* wm1 = (const float4*)(W_mu + (size_t)(cc+1)*HID);
        const float4* wl0 = (const float4*)(W_lv + (size_t)cc*HID);
        const float4* wl1 = (const float4*)(W_lv + (size_t)(cc+1)*HID);
        #pragma unroll
        for (int i = 0; i < 4; i++){
            int k4 = i*32 + l;
            float4 a  = ar[k4];
            float4 m4 = wm0[k4], n4 = wm1[k4], u4 = wl0[k4], v4 = wl1[k4];
            am0=fmaf(a.x,m4.x,am0); am0=fmaf(a.y,m4.y,am0); am0=fmaf(a.z,m4.z,am0); am0=fmaf(a.w,m4.w,am0);
            am1=fmaf(a.x,n4.x,am1); am1=fmaf(a.y,n4.y,am1); am1=fmaf(a.z,n4.z,am1); am1=fmaf(a.w,n4.w,am1);
            al0=fmaf(a.x,u4.x,al0); al0=fmaf(a.y,u4.y,al0); al0=fmaf(a.z,u4.z,al0); al0=fmaf(a.w,u4.w,al0);
            al1=fmaf(a.x,v4.x,al1); al1=fmaf(a.y,v4.y,al1); al1=fmaf(a.z,v4.z,al1); al1=fmaf(a.w,v4.w,al1);
        }
        #pragma unroll
        for (int o = 16; o > 0; o >>= 1){
            am0 += __shfl_down_sync(0xffffffffu, am0, o);
            am1 += __shfl_down_sync(0xffffffffu, am1, o);
            al0 += __shfl_down_sync(0xffffffffu, al0, o);
            al1 += __shfl_down_sync(0xffffffffu, al1, o);
        }
        if (l == 0){
            float mu0 = am0 + b_mu[cc],   lv0 = al0 + b_lv[cc];
            float mu1 = am1 + b_mu[cc+1], lv1 = al1 + b_lv[cc+1];
            out[OUT_ZM + m*LAT + cc]   = mu0;
            out[OUT_ZM + m*LAT + cc+1] = mu1;
            out[OUT_LV + m*LAT + cc]   = lv0;
            out[OUT_LV + m*LAT + cc+1] = lv1;
            g_dz[(size_t)m*IN_DEC + cc]   = mu0 + eps[m*LAT + cc]   * expf(0.5f*lv0);
            g_dz[(size_t)m*IN_DEC + cc+1] = mu1 + eps[m*LAT + cc+1] * expf(0.5f*lv1);
        }
    }
}

// ---------------- K_d2: grid (64,4)=256 blocks; 4 rows x 40 cols per block ----------------
__global__ __launch_bounds__(256) void k_d2(const float* __restrict__ Cp,
        const float* __restrict__ b_d1,
        const float* __restrict__ W_d2, const float* __restrict__ b_d2){
    __shared__ __align__(16) float As[4][HID];
    int m0 = blockIdx.x * 4;
    int tid = threadIdx.x;
    stage_act4(As, Cp, b_d1, m0, tid);
    __syncthreads();
    int w = tid >> 5, l = tid & 31;
    int r = w & 3, h = w >> 2;
    int m = m0 + r;
    const float4* ar = (const float4*)As[r];
    int cbase = blockIdx.y * 40 + h * 20;
    #pragma unroll 1
    for (int pp = 0; pp < 10; pp++){
        int cc = cbase + 2*pp;
        float a0 = 0.f, a1 = 0.f;
        const float4* w0 = (const float4*)(W_d2 + (size_t)cc*HID);
        const float4* w1 = (const float4*)(W_d2 + (size_t)(cc+1)*HID);
        #pragma unroll
        for (int i = 0; i < 4; i++){
            int k4 = i*32 + l;
            float4 a  = ar[k4];
            float4 x0 = w0[k4], x1 = w1[k4];
            a0=fmaf(a.x,x0.x,a0); a0=fmaf(a.y,x0.y,a0); a0=fmaf(a.z,x0.z,a0); a0=fmaf(a.w,x0.w,a0);
            a1=fmaf(a.x,x1.x,a1); a1=fmaf(a.y,x1.y,a1); a1=fmaf(a.z,x1.z,a1); a1=fmaf(a.w,x1.w,a1);
        }
        #pragma unroll
        for (int o = 16; o > 0; o >>= 1){
            a0 += __shfl_down_sync(0xffffffffu, a0, o);
            a1 += __shfl_down_sync(0xffffffffu, a1, o);
        }
        if (l == 0){
            g_rx[(size_t)m*KE + cc]   = fmaxf(a0 + b_d2[cc],   0.f);
            g_rx[(size_t)m*KE + cc+1] = fmaxf(a1 + b_d2[cc+1], 0.f);
        }
    }
}

// ---------------- K_score v7: split chains, unroll 2, NO occupancy cap (no spills) ----------------
// Logit arithmetic identical to v5/v6 (split 8-FMA2 chains + add-merge per row),
// so k_finrec's scalar replay stays bitwise-equal. Exp-sums now accumulate as a
// packed f32x2 pair (order change only affects psum rounding, not argmax).
__global__ __launch_bounds__(256,2) void k_score(const float* __restrict__ emb){
    __shared__ __align__(16) float sh[SUBT * E];   // [pair][dim][item], 16000 B
    int c = blockIdx.x;
    int tid = threadIdx.x;
    int r0 = blockIdx.y * 512 + tid;
    int r1 = r0 + 256;

    ull rxa[E], rxb[E];
    #pragma unroll
    for (int e = 0; e < E; e++){
        rxa[e] = dup2(g_rx[(size_t)r0*E + e] * LOG2E);
        rxb[e] = dup2(g_rx[(size_t)r1*E + e] * LOG2E);
    }
    float m0v = -INFINITY, m1v = -INFINITY;
    ull s0p = 0ull, s1p = 0ull;
    int n0 = c * CHUNK;

    for (int t0 = 0; t0 < CHUNK; t0 += SUBT){
        __syncthreads();
        if (tid < SUBT){
            int n = n0 + t0 + tid;
            const float4* e4 = (const float4*)(emb + (size_t)n * E);
            float* dst = sh + (tid >> 1) * 32 + (tid & 1);
            #pragma unroll
            for (int q = 0; q < 4; q++){
                float4 v = e4[q];
                dst[(4*q+0)*2] = v.x; dst[(4*q+1)*2] = v.y;
                dst[(4*q+2)*2] = v.z; dst[(4*q+3)*2] = v.w;
            }
        }
        __syncthreads();
        const ulonglong2* s2 = (const ulonglong2*)sh;
        #pragma unroll 2
        for (int p = 0; p < SUBT/2; p++){
            ull a0a=0ull, a0b=0ull, a1a=0ull, a1b=0ull;   // 4 independent chains
            #pragma unroll
            for (int e2 = 0; e2 < 4; e2++){               // dims 0-7
                ulonglong2 w = s2[e2];
                asm("fma.rn.f32x2 %0, %1, %2, %0;" : "+l"(a0a) : "l"(w.x), "l"(rxa[2*e2]));
                asm("fma.rn.f32x2 %0, %1, %2, %0;" : "+l"(a0a) : "l"(w.y), "l"(rxa[2*e2+1]));
                asm("fma.rn.f32x2 %0, %1, %2, %0;" : "+l"(a1a) : "l"(w.x), "l"(rxb[2*e2]));
                asm("fma.rn.f32x2 %0, %1, %2, %0;" : "+l"(a1a) : "l"(w.y), "l"(rxb[2*e2+1]));
            }
            #pragma unroll
            for (int e2 = 4; e2 < 8; e2++){               // dims 8-15
                ulonglong2 w = s2[e2];
                asm("fma.rn.f32x2 %0, %1, %2, %0;" : "+l"(a0b) : "l"(w.x), "l"(rxa[2*e2]));
                asm("fma.rn.f32x2 %0, %1, %2, %0;" : "+l"(a0b) : "l"(w.y), "l"(rxa[2*e2+1]));
                asm("fma.rn.f32x2 %0, %1, %2, %0;" : "+l"(a1b) : "l"(w.x), "l"(rxb[2*e2]));
                asm("fma.rn.f32x2 %0, %1, %2, %0;" : "+l"(a1b) : "l"(w.y), "l"(rxb[2*e2+1]));
            }
            s2 += 8;
            ull a0, a1;
            asm("add.rn.f32x2 %0, %1, %2;" : "=l"(a0) : "l"(a0a), "l"(a0b));
            asm("add.rn.f32x2 %0, %1, %2;" : "=l"(a1) : "l"(a1a), "l"(a1b));
            float l0 = p_lo(a0), l1 = p_hi(a0);
            float l2 = p_lo(a1), l3 = p_hi(a1);
            ull e01, e23;
            asm("mov.b64 %0, {%1, %2};" : "=l"(e01) : "f"(ex2f(l0)), "f"(ex2f(l1)));
            asm("mov.b64 %0, {%1, %2};" : "=l"(e23) : "f"(ex2f(l2)), "f"(ex2f(l3)));
            asm("add.rn.f32x2 %0, %1, %2;" : "+l"(s0p) : "l"(s0p), "l"(e01));
            asm("add.rn.f32x2 %0, %1, %2;" : "+l"(s1p) : "l"(s1p), "l"(e23));
            m0v = fmaxf(m0v, l0);  m0v = fmaxf(m0v, l1);
            m1v = fmaxf(m1v, l2);  m1v = fmaxf(m1v, l3);
        }
    }
    g_pmax[c*ROWS + r0] = m0v; g_psum[c*ROWS + r0] = p_lo(s0p) + p_hi(s0p);
    g_pmax[c*ROWS + r1] = m1v; g_psum[c*ROWS + r1] = p_lo(s1p) + p_hi(s1p);
}

// ---------------- K_finrec: combine partials + recover argmax + resp (one warp/row) ----------------
__global__ __launch_bounds__(256) void k_finrec(const float* __restrict__ emb,
                                                const int* __restrict__ slate,
                                                float* __restrict__ out){
    int w = threadIdx.x >> 5, lane = threadIdx.x & 31;
    int r = blockIdx.x * 8 + w;          // 320 blocks x 8 warps = 2560 rows
    // lane-parallel scan over chunks; first-occurrence tie-break by chunk index
    float pm = -INFINITY, T = 0.f;
    int pc = 0;
    #pragma unroll 1
    for (int c = lane; c < NCH; c += 32){
        float v = g_pmax[c*ROWS + r];
        T += g_psum[c*ROWS + r];
        if (v > pm){ pm = v; pc = c; }   // ascending c per lane -> smallest c kept
    }
    #pragma unroll
    for (int o = 16; o > 0; o >>= 1){
        float opm = __shfl_down_sync(0xffffffffu, pm, o);
        int   opc = __shfl_down_sync(0xffffffffu, pc, o);
        float oT  = __shfl_down_sync(0xffffffffu, T,  o);
        T += oT;
        if (opm > pm || (opm == pm && opc < pc)){ pm = opm; pc = opc; }
    }
    float M  = __shfl_sync(0xffffffffu, pm, 0);
    int   wc = __shfl_sync(0xffffffffu, pc, 0);
    T        = __shfl_sync(0xffffffffu, T,  0);

    // rescan winning chunk with exact split-chain replay (== one lane of v7's FMA2)
    float rxs[E];
    const float* rr = g_rx + (size_t)r * E;
    #pragma unroll
    for (int e = 0; e < E; e++) rxs[e] = rr[e] * LOG2E;
    int base = wc * CHUNK;
    int best = 0x7fffffff;
    #pragma unroll 1
    for (int it = 0; it < (CHUNK + 31)/32; it++){
        int n = base + it*32 + lane;
        float lv = -INFINITY;
        if (n < base + CHUNK){
            const float4* ep = (const float4*)(emb + (size_t)n * E);
            float accA = 0.f, accB = 0.f;
            #pragma unroll
            for (int q = 0; q < 2; q++){        // dims 0-7
                float4 v = ep[q];
                accA = fmaf(v.x, rxs[4*q+0], accA);
                accA = fmaf(v.y, rxs[4*q+1], accA);
                accA = fmaf(v.z, rxs[4*q+2], accA);
                accA = fmaf(v.w, rxs[4*q+3], accA);
            }
            #pragma unroll
            for (int q = 2; q < 4; q++){        // dims 8-15
                float4 v = ep[q];
                accB = fmaf(v.x, rxs[4*q+0], accB);
                accB = fmaf(v.y, rxs[4*q+1], accB);
                accB = fmaf(v.z, rxs[4*q+2], accB);
                accB = fmaf(v.w, rxs[4*q+3], accB);
            }
            lv = accA + accB;
        }
        unsigned msk = __ballot_sync(0xffffffffu, lv == M);
        if (msk && best == 0x7fffffff) best = base + it*32 + (__ffs(msk) - 1);
    }
    if (lane == 0){
        out[OUT_SL + r] = (float)best;
        int ns = slate[r];
        const float* er = emb + (size_t)ns * E;
        float dot = 0.f;
        #pragma unroll
        for (int e = 0; e < E; e++) dot += rr[e] * er[e];
        out[OUT_RP + r] = ex2f(dot * LOG2E) / T;
    }
}

// ---------------- launcher ----------------
extern "C" void kernel_launch(void* const* d_in, const int* in_sizes, int n_in,
                              void* d_out, int out_size){
    const int*   ur    = (const int*)  d_in[0];
    const int*   slate = (const int*)  d_in[1];
    const float* resp  = (const float*)d_in[2];
    const float* eps   = (const float*)d_in[3];
    const float* emb   = (const float*)d_in[4];
    const float* W_enc = (const float*)d_in[5];
    const float* b_enc = (const float*)d_in[6];
    const float* W_mu  = (const float*)d_in[7];
    const float* b_mu  = (const float*)d_in[8];
    const float* W_lv  = (const float*)d_in[9];
    const float* b_lv  = (const float*)d_in[10];
    const float* W_d1  = (const float*)d_in[11];
    const float* b_d1  = (const float*)d_in[12];
    const float* W_d2  = (const float*)d_in[13];
    const float* b_d2  = (const float*)d_in[14];
    float* out = (float*)d_out;

    void *px, *pdz, *pp;
    cudaGetSymbolAddress(&px,  g_x);
    cudaGetSymbolAddress(&pdz, g_dz);
    cudaGetSymbolAddress(&pp,  g_part);

    cudaFuncSetAttribute(k_pool, cudaFuncAttributeMaxDynamicSharedMemorySize, SMEM_POOL);

    k_pool<<<dim3(NIC,16), 256, SMEM_POOL>>>(ur, emb);                                   // 0
    k_build<<<B, 256>>>(slate, resp, emb);                                               // 1
    sgemm_part<<<dim3(4,8,4), 256>>>((const float*)px, W_enc, (float*)pp, B, HID, IN_ENC, 304); // 2
    k_mulv<<<dim3(64,4), 256>>>((const float*)pp, b_enc, W_mu, b_mu, W_lv, b_lv, eps, out);     // 3
    sgemm_part<<<dim3(4,8,4), 256>>>((const float*)pdz, W_d1, (float*)pp, B, HID, IN_DEC, 288); // 4
    k_d2<<<dim3(64,4), 256>>>((const float*)pp, b_d1, W_d2, b_d2);                       // 5
    k_score<<<dim3(NCH, ROWS/512), 256>>>(emb);                                          // 6
    k_finrec<<<ROWS/8, 256>>>(emb, slate, out);                                          // 7
}